// round 16
// baseline (speedup 1.0000x reference)
#include <cuda_runtime.h>
#include <cuda_fp16.h>

#define Hd 256
#define Wd 256
#define HWn 65536
#define Bn 4
#define Dn 5
#define Cn 3
#define Sn 27

#define RES_OFF  0L
#define OUT_OFF  (4L*3*3*HWn)
#define SAMP_OFF (OUT_OFF + 4L*3*HWn)

typedef unsigned short u16;
typedef unsigned int u32;

#define GUARD 16        // u32 guard elements before/after each plane region
#define PITCH 264       // u32 per image row in interleaved planes (8 zero gap)
#define CHS   67584     // u32 per channel plane (256 * 264)

// ---------------- interleaved fp16 hi|lo planes (pitched, guarded) --------
// __device__ globals are zero-initialized; the 8-u32 row gaps and guards are
// never written, so halo reads (ww in [-4,-1] or [256,259]) return 0.
__device__ __align__(16) u32 g_data_w[4L*15*CHS + 2*GUARD];
__device__ __align__(16) u32 g_f1_w[4L*64*CHS + 2*GUARD];
__device__ __align__(16) u32 g_feat_w[4L*128*CHS + 2*GUARD];
__device__ __align__(16) u32 g_samp_w[4L*81*CHS + 2*GUARD];
__device__ __align__(16) u32 g_h1_w[4L*64*CHS + 2*GUARD];
__device__ __align__(16) u32 g_h2_w[4L*64*CHS + 2*GUARD];
__device__ float g_off[4L*81*HWn];
__device__ float g_wt[4L*27*HWn];
__device__ uint4 g_bf4[95744];    // fragment-ordered weights {bh0,bh1,bl0,bl1}
__device__ uint2 g_bf2[95744];    // fragment-ordered weights {bh0,bh1} (hi only)

__device__ __forceinline__ u16 f16_hi(float v) {
    __half h = __float2half_rn(v);
    return *reinterpret_cast<u16*>(&h);
}
__device__ __forceinline__ float f16_f(u16 b) {
    __half h = *reinterpret_cast<__half*>(&b);
    return __half2float(h);
}
__device__ __forceinline__ u32 pack_hilo(float v) {
    u16 hv = f16_hi(v);
    u16 lv = f16_hi(v - f16_f(hv));
    return (u32)hv | ((u32)lv << 16);
}
__device__ __forceinline__ u32 smem_u32(const void* p) {
    u32 a;
    asm("{ .reg .u64 t; cvta.to.shared.u64 t, %1; cvt.u32.u64 %0, t; }" : "=r"(a) : "l"(p));
    return a;
}
__device__ __forceinline__ void cp16(u32 dst, const void* src) {
    asm volatile("cp.async.cg.shared.global [%0], [%1], 16;" :: "r"(dst), "l"(src));
}
#define CP_COMMIT() asm volatile("cp.async.commit_group;")

// ---------------------------------------------------------------------------
__global__ void split_k(const float* __restrict__ src, u32* __restrict__ dw, long n)
{
    long i = blockIdx.x * 256L + threadIdx.x;
    if (i >= n) return;
    long row = i >> 8;
    int  w   = (int)(i & 255);
    dw[row * PITCH + w] = pack_hilo(src[i]);
}

// ---------------------------------------------------------------------------
// pack ALL conv weights into mma B-fragment order:
//   uint4 {bh0,bh1,bl0,bl1} (3-term path) and uint2 {bh0,bh1} (2-term path).
// Fragment layout (verified R6-R15): element le = (q*NTt + ng)*32 + lane,
// g=lane>>2, t=lane&3; n = ng*8+g; kb = q*16+2t; pairs (kb,kb+1),(kb+8,kb+9).
// ---------------------------------------------------------------------------
__global__ void packall_k(const float* w0, const float* w1, const float* w2,
                          const float* w3, const float* w4, const float* w5,
                          uint4* __restrict__ bf4, uint2* __restrict__ bf2)
{
    long e = blockIdx.x * 256L + threadIdx.x;
    if (e >= 95744) return;
    int ci; long base;
    if      (e < 3072)  { ci = 0; base = 0; }
    else if (e < 21504) { ci = 1; base = 3072; }
    else if (e < 49152) { ci = 2; base = 21504; }
    else if (e < 81920) { ci = 3; base = 49152; }
    else if (e < 91136) { ci = 4; base = 81920; }
    else                { ci = 5; base = 91136; }
    const float* wp = ci == 0 ? w0 : ci == 1 ? w1 : ci == 2 ? w2
                    : ci == 3 ? w3 : ci == 4 ? w4 : w5;
    const int COUTs[6] = {64, 128, 81, 64, 64, 27};
    const int Ks[6]    = {135, 576, 1152, 2016, 576, 576};
    const int NTts[6]  = {8, 16, 12, 8, 8, 4};
    int COUT = COUTs[ci], K = Ks[ci], NTt = NTts[ci];

    long le = e - base;
    int lane = (int)(le & 31);
    long r = le >> 5;
    int ng = (int)(r % NTt);
    int q  = (int)(r / NTt);
    int g = lane >> 2, t = lane & 3;
    int n = ng * 8 + g;
    int kb = q * 16 + 2 * t;

    float v[4];
    int kk[4] = {kb, kb + 1, kb + 8, kb + 9};
#pragma unroll
    for (int i = 0; i < 4; i++)
        v[i] = (n < COUT && kk[i] < K) ? wp[(long)n * K + kk[i]] : 0.f;

    u16 h[4], l[4];
#pragma unroll
    for (int i = 0; i < 4; i++) {
        h[i] = f16_hi(v[i]);
        l[i] = f16_hi(v[i] - f16_f(h[i]));
    }
    u32 bh0 = (u32)h[0] | ((u32)h[1] << 16);
    u32 bh1 = (u32)h[2] | ((u32)h[3] << 16);
    bf4[e] = make_uint4(bh0, bh1,
                        (u32)l[0] | ((u32)l[1] << 16), (u32)l[2] | ((u32)l[3] << 16));
    bf2[e] = make_uint2(bh0, bh1);
}

// ---------------------------------------------------------------------------
__device__ __forceinline__ void mma16816(float d[4], const u32 a[4], u32 b0, u32 b1)
{
    asm volatile(
        "mma.sync.aligned.m16n8k16.row.col.f32.f16.f16.f32 "
        "{%0,%1,%2,%3}, {%4,%5,%6,%7}, {%8,%9}, {%0,%1,%2,%3};"
        : "+f"(d[0]), "+f"(d[1]), "+f"(d[2]), "+f"(d[3])
        : "r"(a[0]), "r"(a[1]), "r"(a[2]), "r"(a[3]), "r"(b0), "r"(b1));
}

// ---------------------------------------------------------------------------
// Implicit-GEMM 3x3 conv, M=256 (full image row), 512 threads (16 warps),
// each warp owns one m16 strip; NT=4 (32 output channels per block).
// 2 CTA/SM -> 32 warps/SM = 8 warps/SMSP for latency hiding.
// N slice: nbase = blockIdx.y * NT*8.
// A: raw pitched input rows (cin,kh); halo zeros from the row gaps.
//    Fragment offset for kernel column kw is kw + 3 (SMEM idx i <-> ww = i-4).
// B: TERMS==3 -> uint4 frags (LDS.128); TERMS==2 -> uint2 hi-only (LDS.64).
// Pipeline: 2 buffers, one __syncthreads per chunk:
//   wait_group(0) -> sync -> fill(k+1, buf^1) -> mma(k, buf).
// ---------------------------------------------------------------------------
#define A_ROWS   22
#define A_PITCHW 272                         // u32 per SMEM raw row
#define A_CHUNKS 67                          // 16B chunks copied per row
#define A_BUFB   (A_ROWS*A_PITCHW*4)         // 23936 bytes per A buffer
#define NTC      4                           // N tiles per block (fixed)

template<int TERMS>
__global__ void __launch_bounds__(512, 2)
convM_k(const u32* __restrict__ s0, int c0,
        const u32* __restrict__ s1, int c1,
        const u32* __restrict__ s2,
        const uint4* __restrict__ bf4, const uint2* __restrict__ bf2,
        const float* __restrict__ bias,
        u32* __restrict__ dstw, float* __restrict__ dstf,
        int CIN, int COUT, int Kpad, int NTt, int relu)
{
    extern __shared__ char sm[];
    const u32 smbase = smem_u32(sm);
    const int BELEM = (TERMS == 3) ? 16 : 8;
    const int BSZB = 128 * NTC * BELEM;      // bytes per B buffer

    const int tid = threadIdx.x;
    const int wid = tid >> 5;                // 0..15
    const int lane = tid & 31;
    const int g = lane >> 2;
    const int t = lane & 3;
    const int b = blockIdx.x >> 8;
    const int h = blockIdx.x & 255;
    const int nbase = blockIdx.y * (NTC * 8);
    const int ngbase = blockIdx.y * NTC;
    const int mb = wid * 16;

    const int c01 = c0 + c1;
    const int c2 = CIN - c01;
    const int nchunk = Kpad >> 6;

    float acc[NTC][4];
#pragma unroll
    for (int i = 0; i < NTC; i++)
#pragma unroll
        for (int j = 0; j < 4; j++) acc[i][j] = 0.f;

    // ---- fill one chunk's A raw rows + B fragments into buffer `buf` ----
    auto fill = [&](int kc, int buf) {
        const int K0 = kc * 64;
        const int T0 = (int)(((unsigned)K0 * 21846u) >> 16);
        const u32 abase = smbase + buf * A_BUFB;
        // A: 22 rows x 67 16B-chunks (gap supplies halo 0s)
        for (int e = tid; e < A_ROWS * A_CHUNKS; e += 512) {
            int tt = e / A_CHUNKS;
            int j = e - tt * A_CHUNKS;
            int T = T0 + tt;
            int cin = (int)(((unsigned)T * 21846u) >> 16);
            int kh = T - cin * 3;
            int hh = h + kh - 1;
            u32 dst = abase + (u32)(tt * (A_PITCHW * 4) + j * 16);
            if (cin < CIN && (unsigned)hh < 256u) {
                const u32* sp;
                if (cin < c0)       sp = s0 + ((long)b * c0 + cin) * CHS;
                else if (cin < c01) sp = s1 + ((long)b * c1 + (cin - c0)) * CHS;
                else                sp = s2 + ((long)b * c2 + (cin - c01)) * CHS;
                cp16(dst, sp + (long)hh * PITCH + j * 4 - 4);
            } else {
                asm volatile("st.shared.v4.b32 [%0], {%1,%1,%1,%1};" :: "r"(dst), "r"(0u));
            }
        }
        // B fragments
        const u32 bhb = smbase + 2 * A_BUFB + buf * BSZB;
        const int q0 = kc * 4;
        if (TERMS == 3) {
            for (int e = tid; e < 128 * NTC; e += 512) {
                int ks = e / (NTC * 32);
                int r = e - ks * (NTC * 32);
                long fo = ((long)(q0 + ks) * NTt + ngbase) * 32 + r;
                cp16(bhb + (u32)e * 16, bf4 + fo);
            }
        } else {
            for (int e = tid; e < 64 * NTC; e += 512) {
                int ks = e / (NTC * 16);
                int r2 = e - ks * (NTC * 16);
                long fo = ((long)(q0 + ks) * NTt + ngbase) * 32 + r2 * 2;
                cp16(bhb + (u32)e * 16, bf2 + fo);
            }
        }
        CP_COMMIT();
    };

    fill(0, 0);

    for (int kc = 0; kc < nchunk; ++kc) {
        const int buf = kc & 1;
        asm volatile("cp.async.wait_group 0;");   // own fill(kc) complete
        __syncthreads();                          // all fills visible; mma(kc-1) retired

        if (kc + 1 < nchunk)
            fill(kc + 1, buf ^ 1);                // safe: nobody reads buf^1 anymore

        u32* Aw = (u32*)(sm + buf * A_BUFB);
        const char* Bbase = sm + 2 * A_BUFB + buf * BSZB;
        const int K0 = kc * 64;
        const int T0 = (int)(((unsigned)K0 * 21846u) >> 16);

#pragma unroll
        for (int ks = 0; ks < 4; ks++) {
            int kg = K0 + ks * 16 + 2 * t;
            int Ta = (int)(((unsigned)kg * 21846u) >> 16);        int kwa = kg - Ta * 3;
            int Tb = (int)(((unsigned)(kg + 1) * 21846u) >> 16);  int kwb = kg + 1 - Tb * 3;
            int Tc = (int)(((unsigned)(kg + 8) * 21846u) >> 16);  int kwc = kg + 8 - Tc * 3;
            int Td = (int)(((unsigned)(kg + 9) * 21846u) >> 16);  int kwd = kg + 9 - Td * 3;
            int ra = (Ta - T0) * A_PITCHW + kwa + 3;
            int rb = (Tb - T0) * A_PITCHW + kwb + 3;
            int rc = (Tc - T0) * A_PITCHW + kwc + 3;
            int rd = (Td - T0) * A_PITCHW + kwd + 3;

            const int m = mb + g;
            u32 ah[4], al[4];
            {
                u32 x0 = Aw[ra + m],     y0 = Aw[rb + m];
                u32 x1 = Aw[ra + m + 8], y1 = Aw[rb + m + 8];
                u32 x2 = Aw[rc + m],     y2 = Aw[rd + m];
                u32 x3 = Aw[rc + m + 8], y3 = Aw[rd + m + 8];
                ah[0] = __byte_perm(x0, y0, 0x5410); al[0] = __byte_perm(x0, y0, 0x7632);
                ah[1] = __byte_perm(x1, y1, 0x5410); al[1] = __byte_perm(x1, y1, 0x7632);
                ah[2] = __byte_perm(x2, y2, 0x5410); al[2] = __byte_perm(x2, y2, 0x7632);
                ah[3] = __byte_perm(x3, y3, 0x5410); al[3] = __byte_perm(x3, y3, 0x7632);
            }
            if (TERMS == 3) {
                const uint4* Bp = (const uint4*)Bbase + ks * NTC * 32 + lane;
#pragma unroll
                for (int nt = 0; nt < NTC; nt++) {
                    uint4 bv = Bp[nt * 32];
                    mma16816(acc[nt], ah, bv.x, bv.y);
                    mma16816(acc[nt], al, bv.x, bv.y);
                    mma16816(acc[nt], ah, bv.z, bv.w);
                }
            } else {
                const uint2* Bp = (const uint2*)Bbase + ks * NTC * 32 + lane;
#pragma unroll
                for (int nt = 0; nt < NTC; nt++) {
                    uint2 bv = Bp[nt * 32];
                    mma16816(acc[nt], ah, bv.x, bv.y);
                    mma16816(acc[nt], al, bv.x, bv.y);
                }
            }
        }
    }

    // ---- epilogue (pitched dstw, linear dstf) ----
#pragma unroll
    for (int nt = 0; nt < NTC; nt++) {
        int n0 = nbase + nt * 8 + t * 2;
#pragma unroll
        for (int i = 0; i < 4; i++) {
            int n = n0 + (i & 1);
            if (n >= COUT) continue;
            int m = mb + g + ((i & 2) ? 8 : 0);
            float v = acc[nt][i] + bias[n];
            if (relu) v = fmaxf(v, 0.f);
            if (dstw)
                dstw[((long)(b * COUT + n) * 256 + h) * PITCH + m] = pack_hilo(v);
            if (dstf)
                dstf[((long)b * COUT + n) * HWn + (long)h * 256 + m] = v;
        }
    }
}

// ---------------------------------------------------------------------------
__global__ void trilerp_k(const float* __restrict__ data,
                          const float* __restrict__ off,
                          float* __restrict__ samp, u32* __restrict__ sw)
{
    long idx = blockIdx.x * 256L + threadIdx.x;
    if (idx >= (long)Bn * Sn * HWn) return;
    int hw = (int)(idx % HWn);
    int s  = (int)((idx / HWn) % Sn);
    int b  = (int)(idx / ((long)Sn * HWn));
    int h = hw >> 8, w = hw & 255;

    int kd = s / 9 - 1, kh = (s / 3) % 3 - 1, kw = s % 3 - 1;

    const float* ob = off + ((long)b * (Sn * 3) + s * 3) * HWn + hw;
    float pd = 2.0f + (float)kd + ob[0];
    float ph = (float)h + (float)kh + ob[HWn];
    float pw = (float)w + (float)kw + ob[2L * HWn];
    pd = fminf(fmaxf(pd, 0.f), (float)(Dn - 1));
    ph = fminf(fmaxf(ph, 0.f), (float)(Hd - 1));
    pw = fminf(fmaxf(pw, 0.f), (float)(Wd - 1));

    float d0f = floorf(pd), h0f = floorf(ph), w0f = floorf(pw);
    float fd = pd - d0f, fh = ph - h0f, fw = pw - w0f;
    int d0 = (int)d0f, h0 = (int)h0f, w0 = (int)w0f;
    int d1 = min(d0 + 1, Dn - 1), h1 = min(h0 + 1, Hd - 1), w1 = min(w0 + 1, Wd - 1);

    float gd0 = 1.f - fd, gh0 = 1.f - fh, gw0 = 1.f - fw;
    float w000 = gd0*gh0*gw0, w001 = gd0*gh0*fw, w010 = gd0*fh*gw0, w011 = gd0*fh*fw;
    float w100 = fd*gh0*gw0,  w101 = fd*gh0*fw,  w110 = fd*fh*gw0,  w111 = fd*fh*fw;

    long i00 = (long)h0 * Wd + w0, i01 = (long)h0 * Wd + w1;
    long i10 = (long)h1 * Wd + w0, i11 = (long)h1 * Wd + w1;

#pragma unroll
    for (int c = 0; c < Cn; c++) {
        const float* p0 = data + (((long)b * Dn + d0) * Cn + c) * HWn;
        const float* p1 = data + (((long)b * Dn + d1) * Cn + c) * HWn;
        float v = w000*p0[i00] + w001*p0[i01] + w010*p0[i10] + w011*p0[i11]
                + w100*p1[i00] + w101*p1[i01] + w110*p1[i10] + w111*p1[i11];
        samp[(((long)b * Sn + s) * Cn + c) * HWn + hw] = v;
        sw[(((long)(b * Sn + s) * Cn + c) * 256 + h) * PITCH + w] = pack_hilo(v);
    }
}

// ---------------------------------------------------------------------------
__global__ void combine_k(const float* __restrict__ samp,
                          const float* __restrict__ wts,
                          float* __restrict__ res_i, float* __restrict__ outp)
{
    long idx = blockIdx.x * 256L + threadIdx.x;
    if (idx >= (long)Bn * HWn) return;
    int hw = (int)(idx % HWn);
    int b  = (int)(idx / HWn);

    float wv[Sn];
#pragma unroll
    for (int s = 0; s < Sn; s++) wv[s] = wts[((long)b * Sn + s) * HWn + hw];

    float o[3] = {0.f, 0.f, 0.f};
#pragma unroll
    for (int g = 0; g < 3; g++) {
#pragma unroll
        for (int c = 0; c < 3; c++) {
            float r = 0.f;
#pragma unroll
            for (int k = 0; k < 9; k++) {
                int s = g * 9 + k;
                r += samp[(((long)b * Sn + s) * Cn + c) * HWn + hw] * wv[s];
            }
            r *= 3.0f;
            res_i[(((long)b * 3 + g) * 3 + c) * HWn + hw] = r;
            o[c] += r;
        }
    }
#pragma unroll
    for (int c = 0; c < 3; c++)
        outp[((long)b * 3 + c) * HWn + hw] = o[c] * (1.0f / 3.0f);
}

// ---------------------------------------------------------------------------
extern "C" void kernel_launch(void* const* d_in, const int* in_sizes, int n_in,
                              void* d_out, int out_size)
{
    const float* data   = (const float*)d_in[0];
    const float* enc_w1 = (const float*)d_in[1];
    const float* enc_b1 = (const float*)d_in[2];
    const float* enc_w2 = (const float*)d_in[3];
    const float* enc_b2 = (const float*)d_in[4];
    const float* off_w  = (const float*)d_in[5];
    const float* off_b  = (const float*)d_in[6];
    const float* wc_w1  = (const float*)d_in[7];
    const float* wc_b1  = (const float*)d_in[8];
    const float* wc_w2  = (const float*)d_in[9];
    const float* wc_b2  = (const float*)d_in[10];
    const float* wc_w3  = (const float*)d_in[11];
    const float* wc_b3  = (const float*)d_in[12];
    float* out = (float*)d_out;

    u32 *dw, *f1w, *ftw, *spw, *h1w, *h2w;
    float *offs, *wt;
    uint4* bf4;
    uint2* bf2;
    cudaGetSymbolAddress((void**)&dw,  g_data_w);
    cudaGetSymbolAddress((void**)&f1w, g_f1_w);
    cudaGetSymbolAddress((void**)&ftw, g_feat_w);
    cudaGetSymbolAddress((void**)&spw, g_samp_w);
    cudaGetSymbolAddress((void**)&h1w, g_h1_w);
    cudaGetSymbolAddress((void**)&h2w, g_h2_w);
    cudaGetSymbolAddress((void**)&offs, g_off);
    cudaGetSymbolAddress((void**)&wt,  g_wt);
    cudaGetSymbolAddress((void**)&bf4, g_bf4);
    cudaGetSymbolAddress((void**)&bf2, g_bf2);
    dw += GUARD; f1w += GUARD; ftw += GUARD; spw += GUARD; h1w += GUARD; h2w += GUARD;

    float* res_i = out + RES_OFF;
    float* outp  = out + OUT_OFF;
    float* samp  = out + SAMP_OFF;

    // 1) split input data to interleaved fp16 hi|lo pitched plane
    {
        long n = 4L * 15 * HWn;
        split_k<<<(unsigned)((n + 255) / 256), 256>>>(data, dw, n);
    }
    // 2) pack all weights (fragment order, uint4 + uint2 hi-only)
    packall_k<<<(95744 + 255) / 256, 256>>>(enc_w1, enc_w2, off_w,
                                            wc_w1, wc_w2, wc_w3, bf4, bf2);

    const int DSM_3 = 2 * A_BUFB + 2 * 128 * NTC * 16;   // 47872+16384 = 64256
    const int DSM_2 = 2 * A_BUFB + 2 * 128 * NTC * 8;    // 47872+ 8192 = 56064
    cudaFuncSetAttribute(convM_k<3>, cudaFuncAttributeMaxDynamicSharedMemorySize, DSM_3);
    cudaFuncSetAttribute(convM_k<2>, cudaFuncAttributeMaxDynamicSharedMemorySize, DSM_2);

    // 3) f1 = relu(conv(data 15->64)), 3-term, 2 N-slices
    convM_k<3><<<dim3(1024,2), 512, DSM_3>>>(dw, 15, nullptr, 0, nullptr,
        bf4 + 0L, bf2 + 0L, enc_b1, f1w, nullptr, 15, 64, 192, 8, 1);
    // 4) feature = relu(conv(f1 64->128)), 3-term, 4 N-slices
    convM_k<3><<<dim3(1024,4), 512, DSM_3>>>(f1w, 64, nullptr, 0, nullptr,
        bf4 + 3072L, bf2 + 3072L, enc_b2, ftw, nullptr, 64, 128, 576, 16, 1);
    // 5) offsets = conv(feature 128->81) fp32, 2-term, 3 N-slices
    convM_k<2><<<dim3(1024,3), 512, DSM_2>>>(ftw, 128, nullptr, 0, nullptr,
        bf4 + 21504L, bf2 + 21504L, off_b, nullptr, offs, 128, 81, 1152, 12, 0);
    // 6) samples (fp32 to d_out + interleaved pitched plane)
    {
        long n = (long)Bn * Sn * HWn;
        trilerp_k<<<(unsigned)((n + 255) / 256), 256>>>(data, offs, samp, spw);
    }
    // 7) h1 = relu(conv(concat(data15, feat128, samp81) 224->64)), 2-term, 2 slices
    convM_k<2><<<dim3(1024,2), 512, DSM_2>>>(dw, 15, ftw, 128, spw,
        bf4 + 49152L, bf2 + 49152L, wc_b1, h1w, nullptr, 224, 64, 2048, 8, 1);
    // 8) h2 = relu(conv(h1 64->64)), 2-term, 2 slices
    convM_k<2><<<dim3(1024,2), 512, DSM_2>>>(h1w, 64, nullptr, 0, nullptr,
        bf4 + 81920L, bf2 + 81920L, wc_b2, h2w, nullptr, 64, 64, 576, 8, 1);
    // 9) weights = conv(h2 64->27) fp32, 2-term, 1 slice
    convM_k<2><<<dim3(1024,1), 512, DSM_2>>>(h2w, 64, nullptr, 0, nullptr,
        bf4 + 91136L, bf2 + 91136L, wc_b3, nullptr, wt, 64, 27, 576, 4, 0);
    // 10) combine
    {
        long n = (long)Bn * HWn;
        combine_k<<<(unsigned)((n + 255) / 256), 256>>>(samp, wt, res_i, outp);
    }
}

// round 17
// speedup vs baseline: 1.2801x; 1.2801x over previous
#include <cuda_runtime.h>
#include <cuda_fp16.h>

#define Hd 256
#define Wd 256
#define HWn 65536
#define Bn 4
#define Dn 5
#define Cn 3
#define Sn 27

#define RES_OFF  0L
#define OUT_OFF  (4L*3*3*HWn)
#define SAMP_OFF (OUT_OFF + 4L*3*HWn)

typedef unsigned short u16;
typedef unsigned int u32;

#define GUARD 16        // u32 guard elements before/after each plane region
#define PITCH 264       // u32 per image row in interleaved planes (8 zero gap)
#define CHS   67584     // u32 per channel plane (256 * 264)

// ---------------- interleaved fp16 hi|lo planes (pitched, guarded) --------
// __device__ globals are zero-initialized; the 8-u32 row gaps and guards are
// never written, so halo reads (ww in [-4,-1] or [256,259]) return 0.
__device__ __align__(16) u32 g_data_w[4L*15*CHS + 2*GUARD];
__device__ __align__(16) u32 g_f1_w[4L*64*CHS + 2*GUARD];
__device__ __align__(16) u32 g_feat_w[4L*128*CHS + 2*GUARD];
__device__ __align__(16) u32 g_samp_w[4L*81*CHS + 2*GUARD];
__device__ __align__(16) u32 g_h1_w[4L*64*CHS + 2*GUARD];
__device__ __align__(16) u32 g_h2_w[4L*64*CHS + 2*GUARD];
__device__ float g_off[4L*81*HWn];
__device__ float g_wt[4L*27*HWn];
__device__ uint4 g_bf4[95744];    // fragment-ordered weights {bh0,bh1,bl0,bl1}
__device__ uint2 g_bf2[95744];    // fragment-ordered weights {bh0,bh1} (hi only)

__device__ __forceinline__ u16 f16_hi(float v) {
    __half h = __float2half_rn(v);
    return *reinterpret_cast<u16*>(&h);
}
__device__ __forceinline__ float f16_f(u16 b) {
    __half h = *reinterpret_cast<__half*>(&b);
    return __half2float(h);
}
__device__ __forceinline__ u32 pack_hilo(float v) {
    u16 hv = f16_hi(v);
    u16 lv = f16_hi(v - f16_f(hv));
    return (u32)hv | ((u32)lv << 16);
}
__device__ __forceinline__ u32 smem_u32(const void* p) {
    u32 a;
    asm("{ .reg .u64 t; cvta.to.shared.u64 t, %1; cvt.u32.u64 %0, t; }" : "=r"(a) : "l"(p));
    return a;
}
__device__ __forceinline__ void cp16(u32 dst, const void* src) {
    asm volatile("cp.async.cg.shared.global [%0], [%1], 16;" :: "r"(dst), "l"(src));
}
#define CP_COMMIT() asm volatile("cp.async.commit_group;")

// ---------------------------------------------------------------------------
__global__ void split_k(const float* __restrict__ src, u32* __restrict__ dw, long n)
{
    long i = blockIdx.x * 256L + threadIdx.x;
    if (i >= n) return;
    long row = i >> 8;
    int  w   = (int)(i & 255);
    dw[row * PITCH + w] = pack_hilo(src[i]);
}

// ---------------------------------------------------------------------------
// pack ALL conv weights into mma B-fragment order:
//   uint4 {bh0,bh1,bl0,bl1} (3-term path) and uint2 {bh0,bh1} (2-term path).
// Fragment layout (verified R6-R15): element le = (q*NTt + ng)*32 + lane,
// g=lane>>2, t=lane&3; n = ng*8+g; kb = q*16+2t; pairs (kb,kb+1),(kb+8,kb+9).
// ---------------------------------------------------------------------------
__global__ void packall_k(const float* w0, const float* w1, const float* w2,
                          const float* w3, const float* w4, const float* w5,
                          uint4* __restrict__ bf4, uint2* __restrict__ bf2)
{
    long e = blockIdx.x * 256L + threadIdx.x;
    if (e >= 95744) return;
    int ci; long base;
    if      (e < 3072)  { ci = 0; base = 0; }
    else if (e < 21504) { ci = 1; base = 3072; }
    else if (e < 49152) { ci = 2; base = 21504; }
    else if (e < 81920) { ci = 3; base = 49152; }
    else if (e < 91136) { ci = 4; base = 81920; }
    else                { ci = 5; base = 91136; }
    const float* wp = ci == 0 ? w0 : ci == 1 ? w1 : ci == 2 ? w2
                    : ci == 3 ? w3 : ci == 4 ? w4 : w5;
    const int COUTs[6] = {64, 128, 81, 64, 64, 27};
    const int Ks[6]    = {135, 576, 1152, 2016, 576, 576};
    const int NTts[6]  = {8, 16, 12, 8, 8, 4};
    int COUT = COUTs[ci], K = Ks[ci], NTt = NTts[ci];

    long le = e - base;
    int lane = (int)(le & 31);
    long r = le >> 5;
    int ng = (int)(r % NTt);
    int q  = (int)(r / NTt);
    int g = lane >> 2, t = lane & 3;
    int n = ng * 8 + g;
    int kb = q * 16 + 2 * t;

    float v[4];
    int kk[4] = {kb, kb + 1, kb + 8, kb + 9};
#pragma unroll
    for (int i = 0; i < 4; i++)
        v[i] = (n < COUT && kk[i] < K) ? wp[(long)n * K + kk[i]] : 0.f;

    u16 h[4], l[4];
#pragma unroll
    for (int i = 0; i < 4; i++) {
        h[i] = f16_hi(v[i]);
        l[i] = f16_hi(v[i] - f16_f(h[i]));
    }
    u32 bh0 = (u32)h[0] | ((u32)h[1] << 16);
    u32 bh1 = (u32)h[2] | ((u32)h[3] << 16);
    bf4[e] = make_uint4(bh0, bh1,
                        (u32)l[0] | ((u32)l[1] << 16), (u32)l[2] | ((u32)l[3] << 16));
    bf2[e] = make_uint2(bh0, bh1);
}

// ---------------------------------------------------------------------------
__device__ __forceinline__ void mma16816(float d[4], const u32 a[4], u32 b0, u32 b1)
{
    asm volatile(
        "mma.sync.aligned.m16n8k16.row.col.f32.f16.f16.f32 "
        "{%0,%1,%2,%3}, {%4,%5,%6,%7}, {%8,%9}, {%0,%1,%2,%3};"
        : "+f"(d[0]), "+f"(d[1]), "+f"(d[2]), "+f"(d[3])
        : "r"(a[0]), "r"(a[1]), "r"(a[2]), "r"(a[3]), "r"(b0), "r"(b1));
}

// ---------------------------------------------------------------------------
// Implicit-GEMM 3x3 conv, M=256 (full image row), 256 threads, 2 CTA/SM.
// N slice: nbase = (blockIdx.y + ysoff) * NT*8.
// A: raw pitched input rows (cin,kh); halo zeros come free from the row gaps.
//    Fragment offset for kernel column kw is kw + 3 (SMEM idx i <-> ww = i-4).
// B: TERMS==3 -> uint4 frags (LDS.128); TERMS==2 -> uint2 hi-only (LDS.64).
// Pipeline: 2 buffers, ONE __syncthreads per chunk:
//   wait_group(0) -> sync -> fill(k+1, buf^1) -> mma(k, buf).
// ---------------------------------------------------------------------------
#define A_ROWS   22
#define A_PITCHW 272                         // u32 per SMEM raw row
#define A_CHUNKS 67                          // 16B chunks copied per row
#define A_BUFB   (A_ROWS*A_PITCHW*4)         // 23936 bytes per A buffer

template<int NT, int TERMS>
__global__ void __launch_bounds__(256, 2)
convM_k(const u32* __restrict__ s0, int c0,
        const u32* __restrict__ s1, int c1,
        const u32* __restrict__ s2,
        const uint4* __restrict__ bf4, const uint2* __restrict__ bf2,
        const float* __restrict__ bias,
        u32* __restrict__ dstw, float* __restrict__ dstf,
        int CIN, int COUT, int Kpad, int NTt, int ysoff, int relu)
{
    extern __shared__ char sm[];
    const u32 smbase = smem_u32(sm);
    const int BELEM = (TERMS == 3) ? 16 : 8;
    const int BSZB = 128 * NT * BELEM;       // bytes per B buffer

    const int tid = threadIdx.x;
    const int wid = tid >> 5;
    const int lane = tid & 31;
    const int g = lane >> 2;
    const int t = lane & 3;
    const int b = blockIdx.x >> 8;
    const int h = blockIdx.x & 255;
    const int nbase = (blockIdx.y + ysoff) * (NT * 8);
    const int ngbase = (blockIdx.y + ysoff) * NT;
    const int mb = wid * 16;

    const int c01 = c0 + c1;
    const int c2 = CIN - c01;
    const int nchunk = Kpad >> 6;

    float acc[2][NT][4];
#pragma unroll
    for (int mt = 0; mt < 2; mt++)
#pragma unroll
        for (int i = 0; i < NT; i++)
#pragma unroll
            for (int j = 0; j < 4; j++) acc[mt][i][j] = 0.f;

    // ---- fill one chunk's A raw rows + B fragments into buffer `buf` ----
    auto fill = [&](int kc, int buf) {
        const int K0 = kc * 64;
        const int T0 = (int)(((unsigned)K0 * 21846u) >> 16);
        const u32 abase = smbase + buf * A_BUFB;
        // A: 22 rows x 67 16B-chunks, pitched source rows (gap supplies halo 0s)
        for (int e = tid; e < A_ROWS * A_CHUNKS; e += 256) {
            int tt = e / A_CHUNKS;
            int j = e - tt * A_CHUNKS;
            int T = T0 + tt;
            int cin = (int)(((unsigned)T * 21846u) >> 16);
            int kh = T - cin * 3;
            int hh = h + kh - 1;
            u32 dst = abase + (u32)(tt * (A_PITCHW * 4) + j * 16);
            if (cin < CIN && (unsigned)hh < 256u) {
                const u32* sp;
                if (cin < c0)       sp = s0 + ((long)b * c0 + cin) * CHS;
                else if (cin < c01) sp = s1 + ((long)b * c1 + (cin - c0)) * CHS;
                else                sp = s2 + ((long)b * c2 + (cin - c01)) * CHS;
                cp16(dst, sp + (long)hh * PITCH + j * 4 - 4);
            } else {
                asm volatile("st.shared.v4.b32 [%0], {%1,%1,%1,%1};" :: "r"(dst), "r"(0u));
            }
        }
        // B fragments
        const u32 bhb = smbase + 2 * A_BUFB + buf * BSZB;
        const int q0 = kc * 4;
        if (TERMS == 3) {
            for (int e = tid; e < 128 * NT; e += 256) {
                int ks = e / (NT * 32);
                int r = e - ks * (NT * 32);
                long fo = ((long)(q0 + ks) * NTt + ngbase) * 32 + r;
                cp16(bhb + (u32)e * 16, bf4 + fo);
            }
        } else {
            for (int e = tid; e < 64 * NT; e += 256) {
                int ks = e / (NT * 16);
                int r2 = e - ks * (NT * 16);
                long fo = ((long)(q0 + ks) * NTt + ngbase) * 32 + r2 * 2;
                cp16(bhb + (u32)e * 16, bf2 + fo);
            }
        }
        CP_COMMIT();
    };

    fill(0, 0);

    for (int kc = 0; kc < nchunk; ++kc) {
        const int buf = kc & 1;
        asm volatile("cp.async.wait_group 0;");   // own fill(kc) complete
        __syncthreads();                          // all fills visible; mma(kc-1) retired

        if (kc + 1 < nchunk)
            fill(kc + 1, buf ^ 1);                // safe: nobody reads buf^1 anymore

        u32* Aw = (u32*)(sm + buf * A_BUFB);
        const char* Bbase = sm + 2 * A_BUFB + buf * BSZB;
        const int K0 = kc * 64;
        const int T0 = (int)(((unsigned)K0 * 21846u) >> 16);

#pragma unroll
        for (int ks = 0; ks < 4; ks++) {
            int kg = K0 + ks * 16 + 2 * t;
            int Ta = (int)(((unsigned)kg * 21846u) >> 16);        int kwa = kg - Ta * 3;
            int Tb = (int)(((unsigned)(kg + 1) * 21846u) >> 16);  int kwb = kg + 1 - Tb * 3;
            int Tc = (int)(((unsigned)(kg + 8) * 21846u) >> 16);  int kwc = kg + 8 - Tc * 3;
            int Td = (int)(((unsigned)(kg + 9) * 21846u) >> 16);  int kwd = kg + 9 - Td * 3;
            int ra = (Ta - T0) * A_PITCHW + kwa + 3;
            int rb = (Tb - T0) * A_PITCHW + kwb + 3;
            int rc = (Tc - T0) * A_PITCHW + kwc + 3;
            int rd = (Td - T0) * A_PITCHW + kwd + 3;

            u32 ah[2][4], al[2][4];
#pragma unroll
            for (int mt = 0; mt < 2; mt++) {
                int m = mb + mt * 128 + g;
                u32 x0 = Aw[ra + m],     y0 = Aw[rb + m];
                u32 x1 = Aw[ra + m + 8], y1 = Aw[rb + m + 8];
                u32 x2 = Aw[rc + m],     y2 = Aw[rd + m];
                u32 x3 = Aw[rc + m + 8], y3 = Aw[rd + m + 8];
                ah[mt][0] = __byte_perm(x0, y0, 0x5410); al[mt][0] = __byte_perm(x0, y0, 0x7632);
                ah[mt][1] = __byte_perm(x1, y1, 0x5410); al[mt][1] = __byte_perm(x1, y1, 0x7632);
                ah[mt][2] = __byte_perm(x2, y2, 0x5410); al[mt][2] = __byte_perm(x2, y2, 0x7632);
                ah[mt][3] = __byte_perm(x3, y3, 0x5410); al[mt][3] = __byte_perm(x3, y3, 0x7632);
            }
            if (TERMS == 3) {
                const uint4* Bp = (const uint4*)Bbase + ks * NT * 32 + lane;
#pragma unroll
                for (int nt = 0; nt < NT; nt++) {
                    uint4 bv = Bp[nt * 32];
                    mma16816(acc[0][nt], ah[0], bv.x, bv.y);
                    mma16816(acc[0][nt], al[0], bv.x, bv.y);
                    mma16816(acc[1][nt], ah[1], bv.x, bv.y);
                    mma16816(acc[1][nt], al[1], bv.x, bv.y);
                    mma16816(acc[0][nt], ah[0], bv.z, bv.w);
                    mma16816(acc[1][nt], ah[1], bv.z, bv.w);
                }
            } else {
                const uint2* Bp = (const uint2*)Bbase + ks * NT * 32 + lane;
#pragma unroll
                for (int nt = 0; nt < NT; nt++) {
                    uint2 bv = Bp[nt * 32];
                    mma16816(acc[0][nt], ah[0], bv.x, bv.y);
                    mma16816(acc[0][nt], al[0], bv.x, bv.y);
                    mma16816(acc[1][nt], ah[1], bv.x, bv.y);
                    mma16816(acc[1][nt], al[1], bv.x, bv.y);
                }
            }
        }
    }

    // ---- epilogue (pitched dstw, linear dstf) ----
#pragma unroll
    for (int mt = 0; mt < 2; mt++)
#pragma unroll
        for (int nt = 0; nt < NT; nt++) {
            int n0 = nbase + nt * 8 + t * 2;
#pragma unroll
            for (int i = 0; i < 4; i++) {
                int n = n0 + (i & 1);
                if (n >= COUT) continue;
                int m = mb + mt * 128 + g + ((i & 2) ? 8 : 0);
                float v = acc[mt][nt][i] + bias[n];
                if (relu) v = fmaxf(v, 0.f);
                if (dstw)
                    dstw[((long)(b * COUT + n) * 256 + h) * PITCH + m] = pack_hilo(v);
                if (dstf)
                    dstf[((long)b * COUT + n) * HWn + (long)h * 256 + m] = v;
            }
        }
}

// ---------------------------------------------------------------------------
__global__ void trilerp_k(const float* __restrict__ data,
                          const float* __restrict__ off,
                          float* __restrict__ samp, u32* __restrict__ sw)
{
    long idx = blockIdx.x * 256L + threadIdx.x;
    if (idx >= (long)Bn * Sn * HWn) return;
    int hw = (int)(idx % HWn);
    int s  = (int)((idx / HWn) % Sn);
    int b  = (int)(idx / ((long)Sn * HWn));
    int h = hw >> 8, w = hw & 255;

    int kd = s / 9 - 1, kh = (s / 3) % 3 - 1, kw = s % 3 - 1;

    const float* ob = off + ((long)b * (Sn * 3) + s * 3) * HWn + hw;
    float pd = 2.0f + (float)kd + ob[0];
    float ph = (float)h + (float)kh + ob[HWn];
    float pw = (float)w + (float)kw + ob[2L * HWn];
    pd = fminf(fmaxf(pd, 0.f), (float)(Dn - 1));
    ph = fminf(fmaxf(ph, 0.f), (float)(Hd - 1));
    pw = fminf(fmaxf(pw, 0.f), (float)(Wd - 1));

    float d0f = floorf(pd), h0f = floorf(ph), w0f = floorf(pw);
    float fd = pd - d0f, fh = ph - h0f, fw = pw - w0f;
    int d0 = (int)d0f, h0 = (int)h0f, w0 = (int)w0f;
    int d1 = min(d0 + 1, Dn - 1), h1 = min(h0 + 1, Hd - 1), w1 = min(w0 + 1, Wd - 1);

    float gd0 = 1.f - fd, gh0 = 1.f - fh, gw0 = 1.f - fw;
    float w000 = gd0*gh0*gw0, w001 = gd0*gh0*fw, w010 = gd0*fh*gw0, w011 = gd0*fh*fw;
    float w100 = fd*gh0*gw0,  w101 = fd*gh0*fw,  w110 = fd*fh*gw0,  w111 = fd*fh*fw;

    long i00 = (long)h0 * Wd + w0, i01 = (long)h0 * Wd + w1;
    long i10 = (long)h1 * Wd + w0, i11 = (long)h1 * Wd + w1;

#pragma unroll
    for (int c = 0; c < Cn; c++) {
        const float* p0 = data + (((long)b * Dn + d0) * Cn + c) * HWn;
        const float* p1 = data + (((long)b * Dn + d1) * Cn + c) * HWn;
        float v = w000*p0[i00] + w001*p0[i01] + w010*p0[i10] + w011*p0[i11]
                + w100*p1[i00] + w101*p1[i01] + w110*p1[i10] + w111*p1[i11];
        samp[(((long)b * Sn + s) * Cn + c) * HWn + hw] = v;
        sw[(((long)(b * Sn + s) * Cn + c) * 256 + h) * PITCH + w] = pack_hilo(v);
    }
}

// ---------------------------------------------------------------------------
__global__ void combine_k(const float* __restrict__ samp,
                          const float* __restrict__ wts,
                          float* __restrict__ res_i, float* __restrict__ outp)
{
    long idx = blockIdx.x * 256L + threadIdx.x;
    if (idx >= (long)Bn * HWn) return;
    int hw = (int)(idx % HWn);
    int b  = (int)(idx / HWn);

    float wv[Sn];
#pragma unroll
    for (int s = 0; s < Sn; s++) wv[s] = wts[((long)b * Sn + s) * HWn + hw];

    float o[3] = {0.f, 0.f, 0.f};
#pragma unroll
    for (int g = 0; g < 3; g++) {
#pragma unroll
        for (int c = 0; c < 3; c++) {
            float r = 0.f;
#pragma unroll
            for (int k = 0; k < 9; k++) {
                int s = g * 9 + k;
                r += samp[(((long)b * Sn + s) * Cn + c) * HWn + hw] * wv[s];
            }
            r *= 3.0f;
            res_i[(((long)b * 3 + g) * 3 + c) * HWn + hw] = r;
            o[c] += r;
        }
    }
#pragma unroll
    for (int c = 0; c < 3; c++)
        outp[((long)b * 3 + c) * HWn + hw] = o[c] * (1.0f / 3.0f);
}

// ---------------------------------------------------------------------------
extern "C" void kernel_launch(void* const* d_in, const int* in_sizes, int n_in,
                              void* d_out, int out_size)
{
    const float* data   = (const float*)d_in[0];
    const float* enc_w1 = (const float*)d_in[1];
    const float* enc_b1 = (const float*)d_in[2];
    const float* enc_w2 = (const float*)d_in[3];
    const float* enc_b2 = (const float*)d_in[4];
    const float* off_w  = (const float*)d_in[5];
    const float* off_b  = (const float*)d_in[6];
    const float* wc_w1  = (const float*)d_in[7];
    const float* wc_b1  = (const float*)d_in[8];
    const float* wc_w2  = (const float*)d_in[9];
    const float* wc_b2  = (const float*)d_in[10];
    const float* wc_w3  = (const float*)d_in[11];
    const float* wc_b3  = (const float*)d_in[12];
    float* out = (float*)d_out;

    u32 *dw, *f1w, *ftw, *spw, *h1w, *h2w;
    float *offs, *wt;
    uint4* bf4;
    uint2* bf2;
    cudaGetSymbolAddress((void**)&dw,  g_data_w);
    cudaGetSymbolAddress((void**)&f1w, g_f1_w);
    cudaGetSymbolAddress((void**)&ftw, g_feat_w);
    cudaGetSymbolAddress((void**)&spw, g_samp_w);
    cudaGetSymbolAddress((void**)&h1w, g_h1_w);
    cudaGetSymbolAddress((void**)&h2w, g_h2_w);
    cudaGetSymbolAddress((void**)&offs, g_off);
    cudaGetSymbolAddress((void**)&wt,  g_wt);
    cudaGetSymbolAddress((void**)&bf4, g_bf4);
    cudaGetSymbolAddress((void**)&bf2, g_bf2);
    dw += GUARD; f1w += GUARD; ftw += GUARD; spw += GUARD; h1w += GUARD; h2w += GUARD;

    float* res_i = out + RES_OFF;
    float* outp  = out + OUT_OFF;
    float* samp  = out + SAMP_OFF;

    // 1) split input data to interleaved fp16 hi|lo pitched plane
    {
        long n = 4L * 15 * HWn;
        split_k<<<(unsigned)((n + 255) / 256), 256>>>(data, dw, n);
    }
    // 2) pack all weights (fragment order, uint4 + uint2 hi-only)
    packall_k<<<(95744 + 255) / 256, 256>>>(enc_w1, enc_w2, off_w,
                                            wc_w1, wc_w2, wc_w3, bf4, bf2);

    const int DSM_8_3 = 2 * A_BUFB + 2 * 128 * 8 * 16;   // 80640
    const int DSM_8_2 = 2 * A_BUFB + 2 * 128 * 8 * 8;    // 64256
    const int DSM_4_2 = 2 * A_BUFB + 2 * 128 * 4 * 8;    // 56064
    cudaFuncSetAttribute(convM_k<8,3>, cudaFuncAttributeMaxDynamicSharedMemorySize, DSM_8_3);
    cudaFuncSetAttribute(convM_k<8,2>, cudaFuncAttributeMaxDynamicSharedMemorySize, DSM_8_2);
    cudaFuncSetAttribute(convM_k<4,2>, cudaFuncAttributeMaxDynamicSharedMemorySize, DSM_4_2);

    // 3) f1 = relu(conv(data 15->64)), 3-term
    convM_k<8,3><<<dim3(1024,1), 256, DSM_8_3>>>(dw, 15, nullptr, 0, nullptr,
        bf4 + 0L, bf2 + 0L, enc_b1, f1w, nullptr, 15, 64, 192, 8, 0, 1);
    // 4) feature = relu(conv(f1 64->128)), 3-term, 2 N-slices in one launch
    convM_k<8,3><<<dim3(1024,2), 256, DSM_8_3>>>(f1w, 64, nullptr, 0, nullptr,
        bf4 + 3072L, bf2 + 3072L, enc_b2, ftw, nullptr, 64, 128, 576, 16, 0, 1);
    // 5) offsets = conv(feature 128->81) fp32, 2-term: NT8 (n 0..63) + NT4 (n 64..95)
    convM_k<8,2><<<dim3(1024,1), 256, DSM_8_2>>>(ftw, 128, nullptr, 0, nullptr,
        bf4 + 21504L, bf2 + 21504L, off_b, nullptr, offs, 128, 81, 1152, 12, 0, 0);
    convM_k<4,2><<<dim3(1024,1), 256, DSM_4_2>>>(ftw, 128, nullptr, 0, nullptr,
        bf4 + 21504L, bf2 + 21504L, off_b, nullptr, offs, 128, 81, 1152, 12, 2, 0);
    // 6) samples (fp32 to d_out + interleaved pitched plane)
    {
        long n = (long)Bn * Sn * HWn;
        trilerp_k<<<(unsigned)((n + 255) / 256), 256>>>(data, offs, samp, spw);
    }
    // 7) h1 = relu(conv(concat(data15, feat128, samp81) 224->64)), 2-term
    convM_k<8,2><<<dim3(1024,1), 256, DSM_8_2>>>(dw, 15, ftw, 128, spw,
        bf4 + 49152L, bf2 + 49152L, wc_b1, h1w, nullptr, 224, 64, 2048, 8, 0, 1);
    // 8) h2 = relu(conv(h1 64->64)), 2-term
    convM_k<8,2><<<dim3(1024,1), 256, DSM_8_2>>>(h1w, 64, nullptr, 0, nullptr,
        bf4 + 81920L, bf2 + 81920L, wc_b2, h2w, nullptr, 64, 64, 576, 8, 0, 1);
    // 9) weights = conv(h2 64->27) fp32, 2-term
    convM_k<4,2><<<dim3(1024,1), 256, DSM_4_2>>>(h2w, 64, nullptr, 0, nullptr,
        bf4 + 91136L, bf2 + 91136L, wc_b3, nullptr, wt, 64, 27, 576, 4, 0, 0);
    // 10) combine
    {
        long n = (long)Bn * HWn;
        combine_k<<<(unsigned)((n + 255) / 256), 256>>>(samp, wt, res_i, outp);
    }
}